// round 3
// baseline (speedup 1.0000x reference)
#include <cuda_runtime.h>

#define T_STEPS 512
#define BATCH   2048
#define IN_DIM  28
#define H_DIM   64
#define G_DIM   256      // 4*H
#define OUT_DIM 10
#define NB      16       // batch elements per CTA
#define NTHR    256
#define NCTA    (BATCH / NB)   // 128
#define XPAD    36       // xh row stride in floats (144B: 16B-aligned, kills bank conflicts)

// Layer-0 hidden output scratch: [T][B][H] fp32 (256 MB static device array)
__device__ float g_h1[(long long)T_STEPS * BATCH * H_DIM];

static __device__ __forceinline__ float tanh_fast(float x) {
    float y;
    asm("tanh.approx.f32 %0, %1;" : "=f"(y) : "f"(x));
    return y;
}
static __device__ __forceinline__ float sig_fast(float x) {
    return fmaf(0.5f, tanh_fast(0.5f * x), 0.5f);
}
// Packed dual fp32 FMA (Blackwell f32x2 pipe)
static __device__ __forceinline__ void ffma2(unsigned long long& d,
                                             unsigned long long a,
                                             unsigned long long b) {
    asm("fma.rn.f32x2 %0, %1, %2, %0;" : "+l"(d) : "l"(a), "l"(b));
}

// ---------------------------------------------------------------------------
// Layer 0: x[2048,512,28] -> h1[t,b,64] (global scratch)
// ---------------------------------------------------------------------------
__global__ void __launch_bounds__(NTHR, 1)
lstm_l0(const float* __restrict__ x,
        const float* __restrict__ Wih, const float* __restrict__ Whh,
        const float* __restrict__ bih, const float* __restrict__ bhh)
{
    constexpr int KD = IN_DIM + H_DIM;  // 92
    extern __shared__ float sm[];
    float* Ws    = sm;                   // [KD][256]  transposed weights
    float* bias  = Ws + KD * G_DIM;      // [256]
    float* xh    = bias + G_DIM;         // [KD][XPAD] duplicated operands {v,v}
    float* gates = xh + KD * XPAD;       // [256][17]

    const int tid = threadIdx.x;
    const int b0  = blockIdx.x * NB;

    for (int i = tid; i < G_DIM * IN_DIM; i += NTHR) {
        int g = i / IN_DIM, k = i % IN_DIM;
        Ws[k * G_DIM + g] = Wih[i];
    }
    for (int i = tid; i < G_DIM * H_DIM; i += NTHR) {
        int g = i / H_DIM, k = i % H_DIM;
        Ws[(IN_DIM + k) * G_DIM + g] = Whh[i];
    }
    for (int g = tid; g < G_DIM; g += NTHR) bias[g] = bih[g] + bhh[g];
    for (int i = tid; i < H_DIM * XPAD; i += NTHR) xh[IN_DIM * XPAD + i] = 0.0f;
    __syncthreads();

    const int gq = tid >> 2;   // gate quartet 0..63 -> gates [4gq, 4gq+4)
    const int bb = tid & 3;    // batch quad -> b in [4bb, 4bb+4)
    const int uu = tid & 63;   // cell-update hidden unit
    const int cb = tid >> 6;   // cell-update batch lane (0..3)

    unsigned long long bias_p[2];
#pragma unroll
    for (int p = 0; p < 2; p++)
        bias_p[p] = *reinterpret_cast<const unsigned long long*>(bias + gq * 4 + p * 2);

    float c[4];
#pragma unroll
    for (int j = 0; j < 4; j++) c[j] = 0.0f;

    // prefetch x_0  (NB*IN_DIM = 448 items, 2 per thread)
    float xr[2];
#pragma unroll
    for (int j = 0; j < 2; j++) {
        int idx = tid + j * NTHR;
        if (idx < NB * IN_DIM) {
            int bl = idx / IN_DIM, k = idx % IN_DIM;
            xr[j] = x[((long long)(b0 + bl) * T_STEPS) * IN_DIM + k];
        }
    }

    for (int t = 0; t < T_STEPS; t++) {
#pragma unroll
        for (int j = 0; j < 2; j++) {
            int idx = tid + j * NTHR;
            if (idx < NB * IN_DIM) {
                int bl = idx / IN_DIM, k = idx % IN_DIM;
                float2 v = make_float2(xr[j], xr[j]);
                *reinterpret_cast<float2*>(xh + k * XPAD + 2 * bl) = v;
            }
        }
        __syncthreads();   // x_t + h_{t-1} visible

        if (t + 1 < T_STEPS) {
#pragma unroll
            for (int j = 0; j < 2; j++) {
                int idx = tid + j * NTHR;
                if (idx < NB * IN_DIM) {
                    int bl = idx / IN_DIM, k = idx % IN_DIM;
                    xr[j] = x[((long long)(b0 + bl) * T_STEPS + (t + 1)) * IN_DIM + k];
                }
            }
        }

        // gate GEMM: 4 gates x 4 batch per thread
        unsigned long long acc[2][4];
#pragma unroll
        for (int p = 0; p < 2; p++)
#pragma unroll
            for (int q = 0; q < 4; q++) acc[p][q] = bias_p[p];

#pragma unroll 4
        for (int k = 0; k < KD; k++) {
            ulonglong2 wv = *reinterpret_cast<const ulonglong2*>(Ws + k * G_DIM + gq * 4);
            const float* xp = xh + k * XPAD + bb * 8;
            ulonglong2 xv0 = *reinterpret_cast<const ulonglong2*>(xp);
            ulonglong2 xv1 = *reinterpret_cast<const ulonglong2*>(xp + 4);
            unsigned long long xd[4] = {xv0.x, xv0.y, xv1.x, xv1.y};
#pragma unroll
            for (int q = 0; q < 4; q++) ffma2(acc[0][q], wv.x, xd[q]);
#pragma unroll
            for (int q = 0; q < 4; q++) ffma2(acc[1][q], wv.y, xd[q]);
        }

#pragma unroll
        for (int p = 0; p < 2; p++)
#pragma unroll
            for (int q = 0; q < 4; q++) {
                float2 v = *reinterpret_cast<float2*>(&acc[p][q]);
                int g = gq * 4 + 2 * p;
                int b = bb * 4 + q;
                gates[g * 17 + b]       = v.x;
                gates[(g + 1) * 17 + b] = v.y;
            }
        __syncthreads();   // gates visible

        // LSTM cell update: 4 (b,uu) items per thread
#pragma unroll
        for (int j = 0; j < 4; j++) {
            int b = 4 * j + cb;
            float gi = gates[(uu      ) * 17 + b];
            float gf = gates[(uu +  64) * 17 + b];
            float gc = gates[(uu + 128) * 17 + b];
            float go = gates[(uu + 192) * 17 + b];
            float iv = sig_fast(gi);
            float fv = sig_fast(gf);
            float gv = tanh_fast(gc);
            float ov = sig_fast(go);
            float cn = fmaf(fv, c[j], iv * gv);
            c[j] = cn;
            float h = ov * tanh_fast(cn);
            *reinterpret_cast<float2*>(xh + (IN_DIM + uu) * XPAD + 2 * b) = make_float2(h, h);
            g_h1[((long long)t * BATCH + b0 + b) * H_DIM + uu] = h;
        }
        // next x-write hits rows 0..27 (disjoint from h rows); next barrier
        // orders h writes before gate reads.
    }
}

// ---------------------------------------------------------------------------
// Layer 1: h1 (scratch) -> h2; epilogue writes out[2048,10] and r_last[2048,64]
// ---------------------------------------------------------------------------
__global__ void __launch_bounds__(NTHR, 1)
lstm_l1(const float* __restrict__ Wih, const float* __restrict__ Whh,
        const float* __restrict__ bih, const float* __restrict__ bhh,
        const float* __restrict__ Wout, const float* __restrict__ bout,
        float* __restrict__ dout)
{
    constexpr int KD = H_DIM + H_DIM;   // 128
    extern __shared__ float sm[];
    float* Ws    = sm;                   // [128][256]
    float* bias  = Ws + KD * G_DIM;
    float* xh    = bias + G_DIM;         // [128][XPAD]: rows 0..63 h1, 64..127 h2
    float* gates = xh + KD * XPAD;       // [256][17]

    const int tid = threadIdx.x;
    const int b0  = blockIdx.x * NB;

    for (int i = tid; i < G_DIM * H_DIM; i += NTHR) {
        int g = i / H_DIM, k = i % H_DIM;
        Ws[k * G_DIM + g] = Wih[i];
    }
    for (int i = tid; i < G_DIM * H_DIM; i += NTHR) {
        int g = i / H_DIM, k = i % H_DIM;
        Ws[(H_DIM + k) * G_DIM + g] = Whh[i];
    }
    for (int g = tid; g < G_DIM; g += NTHR) bias[g] = bih[g] + bhh[g];
    for (int i = tid; i < H_DIM * XPAD; i += NTHR) xh[H_DIM * XPAD + i] = 0.0f;
    __syncthreads();

    const int gq = tid >> 2;
    const int bb = tid & 3;
    const int uu = tid & 63;
    const int cb = tid >> 6;

    unsigned long long bias_p[2];
#pragma unroll
    for (int p = 0; p < 2; p++)
        bias_p[p] = *reinterpret_cast<const unsigned long long*>(bias + gq * 4 + p * 2);

    float c[4];
#pragma unroll
    for (int j = 0; j < 4; j++) c[j] = 0.0f;

    // prefetch h1_0  (NB*H = 1024 items, 4 per thread)
    float hr[4];
#pragma unroll
    for (int j = 0; j < 4; j++) {
        int idx = tid + j * NTHR;
        int bl = idx >> 6, u = idx & 63;
        hr[j] = g_h1[(long long)(b0 + bl) * H_DIM + u];
    }

    for (int t = 0; t < T_STEPS; t++) {
#pragma unroll
        for (int j = 0; j < 4; j++) {
            int idx = tid + j * NTHR;
            int bl = idx >> 6, u = idx & 63;
            *reinterpret_cast<float2*>(xh + u * XPAD + 2 * bl) = make_float2(hr[j], hr[j]);
        }
        __syncthreads();

        if (t + 1 < T_STEPS) {
#pragma unroll
            for (int j = 0; j < 4; j++) {
                int idx = tid + j * NTHR;
                int bl = idx >> 6, u = idx & 63;
                hr[j] = g_h1[((long long)(t + 1) * BATCH + b0 + bl) * H_DIM + u];
            }
        }

        unsigned long long acc[2][4];
#pragma unroll
        for (int p = 0; p < 2; p++)
#pragma unroll
            for (int q = 0; q < 4; q++) acc[p][q] = bias_p[p];

#pragma unroll 4
        for (int k = 0; k < KD; k++) {
            ulonglong2 wv = *reinterpret_cast<const ulonglong2*>(Ws + k * G_DIM + gq * 4);
            const float* xp = xh + k * XPAD + bb * 8;
            ulonglong2 xv0 = *reinterpret_cast<const ulonglong2*>(xp);
            ulonglong2 xv1 = *reinterpret_cast<const ulonglong2*>(xp + 4);
            unsigned long long xd[4] = {xv0.x, xv0.y, xv1.x, xv1.y};
#pragma unroll
            for (int q = 0; q < 4; q++) ffma2(acc[0][q], wv.x, xd[q]);
#pragma unroll
            for (int q = 0; q < 4; q++) ffma2(acc[1][q], wv.y, xd[q]);
        }

#pragma unroll
        for (int p = 0; p < 2; p++)
#pragma unroll
            for (int q = 0; q < 4; q++) {
                float2 v = *reinterpret_cast<float2*>(&acc[p][q]);
                int g = gq * 4 + 2 * p;
                int b = bb * 4 + q;
                gates[g * 17 + b]       = v.x;
                gates[(g + 1) * 17 + b] = v.y;
            }
        __syncthreads();

#pragma unroll
        for (int j = 0; j < 4; j++) {
            int b = 4 * j + cb;
            float gi = gates[(uu      ) * 17 + b];
            float gf = gates[(uu +  64) * 17 + b];
            float gc = gates[(uu + 128) * 17 + b];
            float go = gates[(uu + 192) * 17 + b];
            float iv = sig_fast(gi);
            float fv = sig_fast(gf);
            float gv = tanh_fast(gc);
            float ov = sig_fast(go);
            float cn = fmaf(fv, c[j], iv * gv);
            c[j] = cn;
            float h = ov * tanh_fast(cn);
            *reinterpret_cast<float2*>(xh + (H_DIM + uu) * XPAD + 2 * b) = make_float2(h, h);
        }
    }
    __syncthreads();   // final h2 visible to all threads

    // r_last -> dout[BATCH*OUT_DIM ...]
#pragma unroll
    for (int j = 0; j < 4; j++) {
        int idx = tid + j * NTHR;
        int bl = idx >> 6, u = idx & 63;
        dout[(long long)BATCH * OUT_DIM + (long long)(b0 + bl) * H_DIM + u] =
            xh[(H_DIM + u) * XPAD + 2 * bl];
    }
    // out = h2 @ Wout^T + bout  (160 items, grid-stride over 256 threads)
    for (int i = tid; i < NB * OUT_DIM; i += NTHR) {
        int bl = i / OUT_DIM, o = i % OUT_DIM;
        float s = bout[o];
#pragma unroll
        for (int u = 0; u < H_DIM; u++)
            s = fmaf(xh[(H_DIM + u) * XPAD + 2 * bl], Wout[o * H_DIM + u], s);
        dout[(long long)(b0 + bl) * OUT_DIM + o] = s;
    }
}

// ---------------------------------------------------------------------------
extern "C" void kernel_launch(void* const* d_in, const int* in_sizes, int n_in,
                              void* d_out, int out_size)
{
    const float* x    = (const float*)d_in[0];
    const float* Wih0 = (const float*)d_in[1];
    const float* Whh0 = (const float*)d_in[2];
    const float* bih0 = (const float*)d_in[3];
    const float* bhh0 = (const float*)d_in[4];
    const float* Wih1 = (const float*)d_in[5];
    const float* Whh1 = (const float*)d_in[6];
    const float* bih1 = (const float*)d_in[7];
    const float* bhh1 = (const float*)d_in[8];
    const float* Wout = (const float*)d_in[9];
    const float* bout = (const float*)d_in[10];
    float* out = (float*)d_out;

    const int smA = ((IN_DIM + H_DIM) * G_DIM + G_DIM + (IN_DIM + H_DIM) * XPAD + G_DIM * 17) * 4;
    const int smB = ((H_DIM + H_DIM) * G_DIM + G_DIM + (H_DIM + H_DIM) * XPAD + G_DIM * 17) * 4;

    cudaFuncSetAttribute(lstm_l0, cudaFuncAttributeMaxDynamicSharedMemorySize, smA);
    cudaFuncSetAttribute(lstm_l1, cudaFuncAttributeMaxDynamicSharedMemorySize, smB);

    lstm_l0<<<NCTA, NTHR, smA>>>(x, Wih0, Whh0, bih0, bhh0);
    lstm_l1<<<NCTA, NTHR, smB>>>(Wih1, Whh1, bih1, bhh1, Wout, bout, out);
}

// round 5
// speedup vs baseline: 1.2775x; 1.2775x over previous
#include <cuda_runtime.h>

#define T_STEPS 512
#define BATCH   2048
#define IN_DIM  28
#define H_DIM   64
#define G_DIM   256      // 4*H
#define OUT_DIM 10
#define NB      16       // batch elements per CTA
#define NTHR    256
#define NCTA    (BATCH / NB)   // 128
#define XPAD    36       // xh row stride (floats); 16B-aligned rows

// Layer-0 hidden output scratch: [T][B][H] fp32
__device__ float g_h1[(long long)T_STEPS * BATCH * H_DIM];

static __device__ __forceinline__ float tanh_fast(float x) {
    float y;
    asm("tanh.approx.f32 %0, %1;" : "=f"(y) : "f"(x));
    return y;
}
static __device__ __forceinline__ float sig_fast(float x) {
    return fmaf(0.5f, tanh_fast(0.5f * x), 0.5f);
}
static __device__ __forceinline__ void ffma2(unsigned long long& d,
                                             unsigned long long a,
                                             unsigned long long b) {
    asm("fma.rn.f32x2 %0, %1, %2, %0;" : "+l"(d) : "l"(a), "l"(b));
}
static __device__ __forceinline__ void fadd2(unsigned long long& d,
                                             unsigned long long a) {
    asm("add.rn.f32x2 %0, %0, %1;" : "+l"(d) : "l"(a));
}
static __device__ __forceinline__ float2 u2f(unsigned long long v) {
    return *reinterpret_cast<float2*>(&v);
}

// Thread map (tid 0..255):
//   bq = tid & 3          -> batch quad (b in [4bq, 4bq+4))
//   go = (tid>>5)*4 + ((tid>>2)&3)   -> u-pair index 0..31 (u = 2go, 2go+1)
//   kh = (tid>>4) & 1     -> k-half (lane bit 4 -> shfl_xor(16) reduction)
// Weight columns permuted: g' = 8*go + e, e = [i u0, i u1, f u0, f u1,
//                                              g u0, g u1, o u0, o u1]
// so acc[p][q] = float2{gate-p(u0), gate-p(u1)} for batch b = 4bq+q,
// with p = 0:i 1:f 2:g 3:o.  Cell update is thread-local.

template<int KD>
static __device__ __forceinline__ void gate_tile(
    const float* __restrict__ Ws, const float* __restrict__ xh,
    const unsigned long long* bias_p, int kh, int go, int bq,
    unsigned long long acc[4][4])
{
    constexpr int KH = KD / 2;
    const int kbeg = kh * KH;

#pragma unroll
    for (int p = 0; p < 4; p++)
#pragma unroll
        for (int q = 0; q < 4; q++)
            acc[p][q] = (kh == 0) ? bias_p[p] : 0ull;

    const float* wr = Ws + kbeg * G_DIM + go * 8;
    const float* xp = xh + kbeg * XPAD + bq * 8;

    ulonglong2 w0a = *reinterpret_cast<const ulonglong2*>(wr);
    ulonglong2 w0b = *reinterpret_cast<const ulonglong2*>(wr + 4);
    ulonglong2 x0a = *reinterpret_cast<const ulonglong2*>(xp);
    ulonglong2 x0b = *reinterpret_cast<const ulonglong2*>(xp + 4);

#pragma unroll 2
    for (int kk = 0; kk < KH; kk++) {
        ulonglong2 w1a, w1b, x1a, x1b;
        if (kk + 1 < KH) {
            const float* wn = wr + (kk + 1) * G_DIM;
            const float* xn = xp + (kk + 1) * XPAD;
            w1a = *reinterpret_cast<const ulonglong2*>(wn);
            w1b = *reinterpret_cast<const ulonglong2*>(wn + 4);
            x1a = *reinterpret_cast<const ulonglong2*>(xn);
            x1b = *reinterpret_cast<const ulonglong2*>(xn + 4);
        }
        unsigned long long wp[4] = {w0a.x, w0a.y, w0b.x, w0b.y};
        unsigned long long xd[4] = {x0a.x, x0a.y, x0b.x, x0b.y};
#pragma unroll
        for (int p = 0; p < 4; p++)
#pragma unroll
            for (int q = 0; q < 4; q++)
                ffma2(acc[p][q], wp[p], xd[q]);
        w0a = w1a; w0b = w1b; x0a = x1a; x0b = x1b;
    }

    // in-warp k-half reduction (lane bit 4)
#pragma unroll
    for (int p = 0; p < 4; p++)
#pragma unroll
        for (int q = 0; q < 4; q++) {
            unsigned long long o = __shfl_xor_sync(0xFFFFFFFFu, acc[p][q], 16);
            fadd2(acc[p][q], o);
        }
}

// permuted column -> original gate row
static __device__ __forceinline__ int gperm(int gp) {
    int e = gp & 7, j = gp >> 3;
    return (e >> 1) * H_DIM + 2 * j + (e & 1);
}

// ---------------------------------------------------------------------------
// Layer 0: x[2048,512,28] -> h1 scratch
// ---------------------------------------------------------------------------
__global__ void __launch_bounds__(NTHR, 1)
lstm_l0(const float* __restrict__ x,
        const float* __restrict__ Wih, const float* __restrict__ Whh,
        const float* __restrict__ bih, const float* __restrict__ bhh)
{
    constexpr int KD = IN_DIM + H_DIM;  // 92
    extern __shared__ float sm[];
    float* Ws   = sm;                    // [KD][256] permuted columns
    float* bias = Ws + KD * G_DIM;       // [256] permuted
    float* xh   = bias + G_DIM;          // [KD][XPAD] dup {v,v}

    const int tid = threadIdx.x;
    const int b0  = blockIdx.x * NB;

    for (int i = tid; i < IN_DIM * G_DIM; i += NTHR) {
        int k = i >> 8, gp = i & 255;
        Ws[k * G_DIM + gp] = Wih[gperm(gp) * IN_DIM + k];
    }
    for (int i = tid; i < H_DIM * G_DIM; i += NTHR) {
        int k = i >> 8, gp = i & 255;
        Ws[(IN_DIM + k) * G_DIM + gp] = Whh[gperm(gp) * H_DIM + k];
    }
    for (int gp = tid; gp < G_DIM; gp += NTHR) {
        int g = gperm(gp);
        bias[gp] = bih[g] + bhh[g];
    }
    for (int i = tid; i < H_DIM * XPAD; i += NTHR) xh[IN_DIM * XPAD + i] = 0.0f;
    __syncthreads();

    const int bq = tid & 3;
    const int go = (tid >> 5) * 4 + ((tid >> 2) & 3);
    const int kh = (tid >> 4) & 1;
    const int u0 = 2 * go;

    unsigned long long bias_p[4];
#pragma unroll
    for (int p = 0; p < 4; p++)
        bias_p[p] = *reinterpret_cast<const unsigned long long*>(bias + go * 8 + 2 * p);

    float c[4];   // [qq][du]
#pragma unroll
    for (int j = 0; j < 4; j++) c[j] = 0.0f;

    // prefetch x_0 (448 items)
    float xr[2];
#pragma unroll
    for (int j = 0; j < 2; j++) {
        int idx = tid + j * NTHR;
        if (idx < NB * IN_DIM) {
            int bl = idx / IN_DIM, k = idx % IN_DIM;
            xr[j] = x[((long long)(b0 + bl) * T_STEPS) * IN_DIM + k];
        }
    }

    for (int t = 0; t < T_STEPS; t++) {
#pragma unroll
        for (int j = 0; j < 2; j++) {
            int idx = tid + j * NTHR;
            if (idx < NB * IN_DIM) {
                int bl = idx / IN_DIM, k = idx % IN_DIM;
                *reinterpret_cast<float2*>(xh + k * XPAD + 2 * bl) =
                    make_float2(xr[j], xr[j]);
            }
        }
        __syncthreads();   // bar1: x_t + h_{t-1} visible

        if (t + 1 < T_STEPS) {
#pragma unroll
            for (int j = 0; j < 2; j++) {
                int idx = tid + j * NTHR;
                if (idx < NB * IN_DIM) {
                    int bl = idx / IN_DIM, k = idx % IN_DIM;
                    xr[j] = x[((long long)(b0 + bl) * T_STEPS + (t + 1)) * IN_DIM + k];
                }
            }
        }

        unsigned long long acc[4][4];
        gate_tile<KD>(Ws, xh, bias_p, kh, go, bq, acc);

        // thread-local cell update for 2 batches x 2 units
        float hv[4];
        int   bv[2];
#pragma unroll
        for (int qq = 0; qq < 2; qq++) {
            int q = kh * 2 + qq;
            int b = bq * 4 + kh * 2 + qq;
            bv[qq] = b;
            float2 iv = u2f(acc[0][q]), fv = u2f(acc[1][q]);
            float2 gv = u2f(acc[2][q]), ov = u2f(acc[3][q]);
#pragma unroll
            for (int du = 0; du < 2; du++) {
                float i_ = sig_fast(du ? iv.y : iv.x);
                float f_ = sig_fast(du ? fv.y : fv.x);
                float g_ = tanh_fast(du ? gv.y : gv.x);
                float o_ = sig_fast(du ? ov.y : ov.x);
                float cn = fmaf(f_, c[qq * 2 + du], i_ * g_);
                c[qq * 2 + du] = cn;
                hv[qq * 2 + du] = o_ * tanh_fast(cn);
            }
        }
        __syncthreads();   // bar2: all xh reads of step t done before h writes

#pragma unroll
        for (int qq = 0; qq < 2; qq++) {
            int b = bv[qq];
#pragma unroll
            for (int du = 0; du < 2; du++) {
                float h = hv[qq * 2 + du];
                *reinterpret_cast<float2*>(xh + (IN_DIM + u0 + du) * XPAD + 2 * b) =
                    make_float2(h, h);
                g_h1[((long long)t * BATCH + b0 + b) * H_DIM + (u0 + du)] = h;
            }
        }
        // bar1 of next iteration orders these stores before next gemm reads
    }
}

// ---------------------------------------------------------------------------
// Layer 1: h1 -> h2; writes out[2048,10] and r_last[2048,64]
// ---------------------------------------------------------------------------
__global__ void __launch_bounds__(NTHR, 1)
lstm_l1(const float* __restrict__ Wih, const float* __restrict__ Whh,
        const float* __restrict__ bih, const float* __restrict__ bhh,
        const float* __restrict__ Wout, const float* __restrict__ bout,
        float* __restrict__ dout)
{
    constexpr int KD = H_DIM + H_DIM;   // 128
    extern __shared__ float sm[];
    float* Ws   = sm;                    // [128][256] permuted
    float* bias = Ws + KD * G_DIM;
    float* xh   = bias + G_DIM;          // [128][XPAD]: rows 0..63 h1, 64..127 h2

    const int tid = threadIdx.x;
    const int b0  = blockIdx.x * NB;

    for (int i = tid; i < H_DIM * G_DIM; i += NTHR) {
        int k = i >> 8, gp = i & 255;
        Ws[k * G_DIM + gp] = Wih[gperm(gp) * H_DIM + k];
    }
    for (int i = tid; i < H_DIM * G_DIM; i += NTHR) {
        int k = i >> 8, gp = i & 255;
        Ws[(H_DIM + k) * G_DIM + gp] = Whh[gperm(gp) * H_DIM + k];
    }
    for (int gp = tid; gp < G_DIM; gp += NTHR) {
        int g = gperm(gp);
        bias[gp] = bih[g] + bhh[g];
    }
    for (int i = tid; i < H_DIM * XPAD; i += NTHR) xh[H_DIM * XPAD + i] = 0.0f;
    __syncthreads();

    const int bq = tid & 3;
    const int go = (tid >> 5) * 4 + ((tid >> 2) & 3);
    const int kh = (tid >> 4) & 1;
    const int u0 = 2 * go;

    unsigned long long bias_p[4];
#pragma unroll
    for (int p = 0; p < 4; p++)
        bias_p[p] = *reinterpret_cast<const unsigned long long*>(bias + go * 8 + 2 * p);

    float c[4];
#pragma unroll
    for (int j = 0; j < 4; j++) c[j] = 0.0f;

    // prefetch h1_0 (1024 items, coalesced)
    float hr[4];
#pragma unroll
    for (int j = 0; j < 4; j++) {
        int idx = tid + j * NTHR;
        int bl = idx >> 6, u = idx & 63;
        hr[j] = g_h1[(long long)(b0 + bl) * H_DIM + u];
    }

    for (int t = 0; t < T_STEPS; t++) {
#pragma unroll
        for (int j = 0; j < 4; j++) {
            int idx = tid + j * NTHR;
            int bl = idx >> 6, u = idx & 63;
            *reinterpret_cast<float2*>(xh + u * XPAD + 2 * bl) =
                make_float2(hr[j], hr[j]);
        }
        __syncthreads();   // bar1

        if (t + 1 < T_STEPS) {
#pragma unroll
            for (int j = 0; j < 4; j++) {
                int idx = tid + j * NTHR;
                int bl = idx >> 6, u = idx & 63;
                hr[j] = g_h1[((long long)(t + 1) * BATCH + b0 + bl) * H_DIM + u];
            }
        }

        unsigned long long acc[4][4];
        gate_tile<KD>(Ws, xh, bias_p, kh, go, bq, acc);

        float hv[4];
        int   bv[2];
#pragma unroll
        for (int qq = 0; qq < 2; qq++) {
            int q = kh * 2 + qq;
            int b = bq * 4 + kh * 2 + qq;
            bv[qq] = b;
            float2 iv = u2f(acc[0][q]), fv = u2f(acc[1][q]);
            float2 gv = u2f(acc[2][q]), ov = u2f(acc[3][q]);
#pragma unroll
            for (int du = 0; du < 2; du++) {
                float i_ = sig_fast(du ? iv.y : iv.x);
                float f_ = sig_fast(du ? fv.y : fv.x);
                float g_ = tanh_fast(du ? gv.y : gv.x);
                float o_ = sig_fast(du ? ov.y : ov.x);
                float cn = fmaf(f_, c[qq * 2 + du], i_ * g_);
                c[qq * 2 + du] = cn;
                hv[qq * 2 + du] = o_ * tanh_fast(cn);
            }
        }
        __syncthreads();   // bar2

#pragma unroll
        for (int qq = 0; qq < 2; qq++) {
            int b = bv[qq];
#pragma unroll
            for (int du = 0; du < 2; du++) {
                float h = hv[qq * 2 + du];
                *reinterpret_cast<float2*>(xh + (H_DIM + u0 + du) * XPAD + 2 * b) =
                    make_float2(h, h);
            }
        }
    }
    __syncthreads();   // final h2 visible

    // r_last
#pragma unroll
    for (int j = 0; j < 4; j++) {
        int idx = tid + j * NTHR;
        int bl = idx >> 6, u = idx & 63;
        dout[(long long)BATCH * OUT_DIM + (long long)(b0 + bl) * H_DIM + u] =
            xh[(H_DIM + u) * XPAD + 2 * bl];
    }
    // out = h2 @ Wout^T + bout (160 items over 256 threads)
    for (int i = tid; i < NB * OUT_DIM; i += NTHR) {
        int bl = i / OUT_DIM, o = i % OUT_DIM;
        float s = bout[o];
#pragma unroll
        for (int u = 0; u < H_DIM; u++)
            s = fmaf(xh[(H_DIM + u) * XPAD + 2 * bl], Wout[o * H_DIM + u], s);
        dout[(long long)(b0 + bl) * OUT_DIM + o] = s;
    }
}

// ---------------------------------------------------------------------------
extern "C" void kernel_launch(void* const* d_in, const int* in_sizes, int n_in,
                              void* d_out, int out_size)
{
    const float* x    = (const float*)d_in[0];
    const float* Wih0 = (const float*)d_in[1];
    const float* Whh0 = (const float*)d_in[2];
    const float* bih0 = (const float*)d_in[3];
    const float* bhh0 = (const float*)d_in[4];
    const float* Wih1 = (const float*)d_in[5];
    const float* Whh1 = (const float*)d_in[6];
    const float* bih1 = (const float*)d_in[7];
    const float* bhh1 = (const float*)d_in[8];
    const float* Wout = (const float*)d_in[9];
    const float* bout = (const float*)d_in[10];
    float* out = (float*)d_out;

    const int KD0 = IN_DIM + H_DIM, KD1 = 2 * H_DIM;
    const int smA = (KD0 * G_DIM + G_DIM + KD0 * XPAD) * 4;
    const int smB = (KD1 * G_DIM + G_DIM + KD1 * XPAD) * 4;

    cudaFuncSetAttribute(lstm_l0, cudaFuncAttributeMaxDynamicSharedMemorySize, smA);
    cudaFuncSetAttribute(lstm_l1, cudaFuncAttributeMaxDynamicSharedMemorySize, smB);

    lstm_l0<<<NCTA, NTHR, smA>>>(x, Wih0, Whh0, bih0, bhh0);
    lstm_l1<<<NCTA, NTHR, smB>>>(Wih1, Whh1, bih1, bhh1, Wout, bout, out);
}